// round 7
// baseline (speedup 1.0000x reference)
#include <cuda_runtime.h>
#include <cuda_bf16.h>
#include <cstdint>

#define QT 16384
#define ST 16384
#define DD 1024
#define NL 64
#define KSLABS 32          // token slabs (512 tokens each)
#define NBLK   8           // dim blocks (128 dims each)

// ---- scratch (device globals; no allocation allowed) ----
__device__ float          g_part[KSLABS * NL * DD];   // 8 MB partial sums
__device__ float          g_counts[NL];
__device__ __nv_bfloat16  g_protobf[NL * DD];
__device__ float          g_p2[NL];

__device__ __forceinline__ unsigned smem_u32(const void* p) {
    return (unsigned)__cvta_generic_to_shared(p);
}
#define CP16(dst, src) asm volatile("cp.async.cg.shared.global [%0], [%1], 16;\n" :: "r"(dst), "l"(src))
#define CPCOMMIT()     asm volatile("cp.async.commit_group;\n")
#define CPWAIT(n)      asm volatile("cp.async.wait_group %0;\n" :: "n"(n))

// ============================================================
// k_zero: zero counts + p2
// ============================================================
__global__ void k_zero() {
    int i = threadIdx.x;
    if (i < NL) { g_counts[i] = 0.f; g_p2[i] = 0.f; }
}

// ============================================================
// k_cnt: masked label histogram. grid 64 x 256 thr.
// ============================================================
__global__ void k_cnt(const int* __restrict__ tag, const int* __restrict__ msk) {
    __shared__ int cnt[NL];
    int t = threadIdx.x;
    if (t < NL) cnt[t] = 0;
    __syncthreads();
    int tk = blockIdx.x * 256 + t;
    if (msk[tk]) atomicAdd(&cnt[tag[tk]], 1);
    __syncthreads();
    if (t < NL && cnt[t]) atomicAdd(&g_counts[t], (float)cnt[t]);
}

// ============================================================
// k_acc2: proto partial sums as tf32 GEMM, cp.async 3-stage.
// grid (NBLK=8, KSLABS=32) = 256 CTAs, 256 threads (8 warps).
// CTA tile: M=64 labels x N=128 dims, K=512 tokens, chunks of 32.
// ============================================================
__global__ void __launch_bounds__(256, 2) k_acc2(const float* __restrict__ emb,
                                                 const int* __restrict__ tag,
                                                 const int* __restrict__ msk) {
    __shared__ float emb_s[3][32][136];  // 52.2 KB
    __shared__ int   tm_s[3][64];        // [0..31] tag, [32..63] msk

    int t = threadIdx.x;
    int nb = blockIdx.x;                 // dim block 0..7
    int sl = blockIdx.y;                 // token slab 0..31
    int w = t >> 5, l = t & 31;
    int g = l >> 2, tq = l & 3;
    int srow = t >> 3, sseg = t & 7;     // stager: 8 x 16B segs per token row
    int nc0 = w * 16;                    // warp dim offset within 128

    const float* ebase = emb + (size_t)(sl * 512) * DD + nb * 128;
    const int* tbase = tag + sl * 512;
    const int* mbase = msk + sl * 512;

    float acc[4][2][4];
    #pragma unroll
    for (int a = 0; a < 4; a++)
        #pragma unroll
        for (int b = 0; b < 2; b++)
            #pragma unroll
            for (int c = 0; c < 4; c++) acc[a][b][c] = 0.f;

    auto issue = [&](int c, int buf) {
        const float* rp = ebase + (size_t)(c * 32 + srow) * DD;
        #pragma unroll
        for (int p = 0; p < 4; p++)
            CP16(smem_u32(&emb_s[buf][srow][(sseg + p * 8) * 4]),
                 rp + (sseg + p * 8) * 4);
        // 32 tags = 8 thr x 4 ints; 32 msks = 8 thr x 4 ints
        if (t < 8)       CP16(smem_u32(&tm_s[buf][t * 4]),
                              tbase + c * 32 + t * 4);
        else if (t < 16) CP16(smem_u32(&tm_s[buf][32 + (t - 8) * 4]),
                              mbase + c * 32 + (t - 8) * 4);
        CPCOMMIT();
    };

    issue(0, 0);
    issue(1, 1);

    for (int c = 0; c < 16; c++) {
        if (c < 15) { CPWAIT(1); } else { CPWAIT(0); }
        __syncthreads();
        if (c < 14) issue(c + 2, (c + 2) % 3);
        int cb = c % 3;
        #pragma unroll
        for (int ks = 0; ks < 4; ks++) {
            int k0 = ks * 8;
            int r0 = tm_s[cb][k0 + tq],      m0 = tm_s[cb][32 + k0 + tq];
            int r1 = tm_s[cb][k0 + tq + 4],  m1 = tm_s[cb][32 + k0 + tq + 4];
            int t0 = m0 ? r0 : -1;
            int t1 = m1 ? r1 : -1;
            unsigned b[2][2];
            #pragma unroll
            for (int nt = 0; nt < 2; nt++) {
                b[nt][0] = __float_as_uint(emb_s[cb][k0 + tq][nc0 + nt * 8 + g]);
                b[nt][1] = __float_as_uint(emb_s[cb][k0 + tq + 4][nc0 + nt * 8 + g]);
            }
            #pragma unroll
            for (int mt = 0; mt < 4; mt++) {
                int mlo = mt * 16 + g, mhi = mlo + 8;
                unsigned a0 = (t0 == mlo) ? 0x3F800000u : 0u;
                unsigned a1 = (t0 == mhi) ? 0x3F800000u : 0u;
                unsigned a2 = (t1 == mlo) ? 0x3F800000u : 0u;
                unsigned a3 = (t1 == mhi) ? 0x3F800000u : 0u;
                #pragma unroll
                for (int nt = 0; nt < 2; nt++)
                    asm volatile(
                        "mma.sync.aligned.m16n8k8.row.col.f32.tf32.tf32.f32 "
                        "{%0,%1,%2,%3}, {%4,%5,%6,%7}, {%8,%9}, {%0,%1,%2,%3};\n"
                        : "+f"(acc[mt][nt][0]), "+f"(acc[mt][nt][1]),
                          "+f"(acc[mt][nt][2]), "+f"(acc[mt][nt][3])
                        : "r"(a0), "r"(a1), "r"(a2), "r"(a3),
                          "r"(b[nt][0]), "r"(b[nt][1]));
            }
        }
    }

    // ---- write partial tile: g_part[sl][m][nb*128 + n] ----
    float* pb = g_part + (size_t)sl * NL * DD + nb * 128;
    #pragma unroll
    for (int mt = 0; mt < 4; mt++) {
        int mlo = mt * 16 + g, mhi = mlo + 8;
        #pragma unroll
        for (int nt = 0; nt < 2; nt++) {
            int col = nc0 + nt * 8 + 2 * tq;
            float2 lo = make_float2(acc[mt][nt][0], acc[mt][nt][1]);
            float2 hi = make_float2(acc[mt][nt][2], acc[mt][nt][3]);
            *reinterpret_cast<float2*>(pb + (size_t)mlo * DD + col) = lo;
            *reinterpret_cast<float2*>(pb + (size_t)mhi * DD + col) = hi;
        }
    }
}

// ============================================================
// k_fin2: reduce slabs, divide by counts, emit bf16 proto + p2.
// grid (64 labels, 8 dim-chunks) = 512 CTAs, 128 threads.
// ============================================================
__global__ void __launch_bounds__(128) k_fin2() {
    int n = blockIdx.x, ch = blockIdx.y, t = threadIdx.x;
    int d = ch * 128 + t;
    float s = 0.f;
    const float* pp = g_part + (size_t)n * DD + d;
    #pragma unroll
    for (int sl = 0; sl < KSLABS; sl++)
        s += pp[(size_t)sl * NL * DD];
    float v = s / fmaxf(g_counts[n], 1.f);
    g_protobf[n * DD + d] = __float2bfloat16_rn(v);
    float ps = v * v;
    #pragma unroll
    for (int o = 16; o; o >>= 1) ps += __shfl_xor_sync(0xffffffffu, ps, o);
    if ((t & 31) == 0) atomicAdd(&g_p2[n], ps);
}

// ============================================================
// k_main: 32 tokens x 64 protos per block, 128 threads (4 warps).
// 2-chunk-deep register q prefetch + 3-buffer smem; proto via
// cp.async 3-stage. grid = 512.
// ============================================================
__global__ void __launch_bounds__(128, 4) k_main(const float* __restrict__ q,
                                                 const int* __restrict__ qmsk,
                                                 float* __restrict__ out) {
    __shared__ __nv_bfloat16 q_sh[3][32][72];   // 13.5 KB
    __shared__ __nv_bfloat16 p_sh[3][64][72];   // 27 KB
    __shared__ float q2_sh[32], p2_sh[64];
    __shared__ int   msk_sh[32];

    int t = threadIdx.x;
    int tok0 = blockIdx.x * 32;
    if (t < 64) p2_sh[t] = g_p2[t];
    if (t >= 64 && t < 96) msk_sh[t - 64] = qmsk[tok0 + t - 64];

    int warp = t >> 5, l = t & 31;
    int wm = warp >> 1, wn = warp & 1;
    int g = l >> 2, kb = (l & 3) * 2;
    int lt = t >> 4, kv = t & 15;       // q loader: 16 thr per token row
    int prow = t >> 3, pseg = t & 7;    // proto cp.async mapping

    const float* qbase = q + (size_t)tok0 * DD;

    float acc[4][4];
    #pragma unroll
    for (int b = 0; b < 4; b++)
        #pragma unroll
        for (int cc = 0; cc < 4; cc++) acc[b][cc] = 0.f;
    float q2p[4] = {0.f, 0.f, 0.f, 0.f};

    float4 vreg[2][4];                  // 2-deep register staging for q

    auto load_q = [&](int c, int rb) {
        #pragma unroll
        for (int p = 0; p < 4; p++)
            vreg[rb][p] = *reinterpret_cast<const float4*>(
                qbase + (size_t)(p * 8 + lt) * DD + c * 64 + kv * 4);
    };
    auto issue_p = [&](int c, int buf) {
        #pragma unroll
        for (int p = 0; p < 4; p++)
            CP16(smem_u32(&p_sh[buf][p * 16 + prow][pseg * 8]),
                 &g_protobf[(p * 16 + prow) * DD + c * 64 + pseg * 8]);
        CPCOMMIT();
    };
    auto store_q = [&](int rb, int buf) {
        #pragma unroll
        for (int p = 0; p < 4; p++) {
            float4 v = vreg[rb][p];
            q2p[p] += v.x * v.x + v.y * v.y + v.z * v.z + v.w * v.w;
            __nv_bfloat162 h0 = __floats2bfloat162_rn(v.x, v.y);
            __nv_bfloat162 h1 = __floats2bfloat162_rn(v.z, v.w);
            uint2 u;
            u.x = reinterpret_cast<unsigned&>(h0);
            u.y = reinterpret_cast<unsigned&>(h1);
            *reinterpret_cast<uint2*>(&q_sh[buf][p * 8 + lt][kv * 4]) = u;
        }
    };

    // prologue: chunks 0,1 in flight
    load_q(0, 0);
    load_q(1, 1);
    issue_p(0, 0);
    issue_p(1, 1);
    store_q(0, 0);

    for (int c = 0; c < 16; c++) {
        if (c < 15) { CPWAIT(1); } else { CPWAIT(0); }   // proto buf c ready
        __syncthreads();
        if (c < 14) {
            issue_p(c + 2, (c + 2) % 3);
            load_q(c + 2, c & 1);       // reg buf freed by chunk c's store
        }
        int cb = c % 3;
        #pragma unroll
        for (int s = 0; s < 4; s++) {
            int k0 = s * 16 + kb;
            unsigned a[4], b[4][2];
            {
                int r = wm * 16 + g;
                a[0] = *reinterpret_cast<const unsigned*>(&q_sh[cb][r][k0]);
                a[1] = *reinterpret_cast<const unsigned*>(&q_sh[cb][r + 8][k0]);
                a[2] = *reinterpret_cast<const unsigned*>(&q_sh[cb][r][k0 + 8]);
                a[3] = *reinterpret_cast<const unsigned*>(&q_sh[cb][r + 8][k0 + 8]);
            }
            #pragma unroll
            for (int nt = 0; nt < 4; nt++) {
                int n0 = wn * 32 + nt * 8 + g;
                b[nt][0] = *reinterpret_cast<const unsigned*>(&p_sh[cb][n0][k0]);
                b[nt][1] = *reinterpret_cast<const unsigned*>(&p_sh[cb][n0][k0 + 8]);
            }
            #pragma unroll
            for (int nt = 0; nt < 4; nt++)
                asm volatile(
                    "mma.sync.aligned.m16n8k16.row.col.f32.bf16.bf16.f32 "
                    "{%0,%1,%2,%3}, {%4,%5,%6,%7}, {%8,%9}, {%0,%1,%2,%3};\n"
                    : "+f"(acc[nt][0]), "+f"(acc[nt][1]),
                      "+f"(acc[nt][2]), "+f"(acc[nt][3])
                    : "r"(a[0]), "r"(a[1]), "r"(a[2]), "r"(a[3]),
                      "r"(b[nt][0]), "r"(b[nt][1]));
        }
        if (c < 15) store_q((c + 1) & 1, (c + 1) % 3);
    }

    // ---- fold per-thread q2 partials (16 lanes per token row) ----
    #pragma unroll
    for (int p = 0; p < 4; p++) {
        float vv = q2p[p];
        vv += __shfl_xor_sync(0xffffffffu, vv, 8);
        vv += __shfl_xor_sync(0xffffffffu, vv, 4);
        vv += __shfl_xor_sync(0xffffffffu, vv, 2);
        vv += __shfl_xor_sync(0xffffffffu, vv, 1);
        if (kv == 0) q2_sh[p * 8 + lt] = vv;
    }
    __syncthreads();

    // ---- epilogue ----
    {
        int r0 = wm * 16 + g;
        int r1 = r0 + 8;
        float m0 = (float)msk_sh[r0], m1 = (float)msk_sh[r1];
        float q20 = q2_sh[r0], q21 = q2_sh[r1];
        #pragma unroll
        for (int nt = 0; nt < 4; nt++) {
            int cc = wn * 32 + nt * 8 + kb;
            float p20 = p2_sh[cc], p21 = p2_sh[cc + 1];
            float2 o0, o1;
            o0.x = -(q20 + p20 - 2.f * acc[nt][0]) * m0;
            o0.y = -(q20 + p21 - 2.f * acc[nt][1]) * m0;
            o1.x = -(q21 + p20 - 2.f * acc[nt][2]) * m1;
            o1.y = -(q21 + p21 - 2.f * acc[nt][3]) * m1;
            *reinterpret_cast<float2*>(out + (size_t)(tok0 + r0) * NL + cc) = o0;
            *reinterpret_cast<float2*>(out + (size_t)(tok0 + r1) * NL + cc) = o1;
        }
    }
}

// ============================================================
extern "C" void kernel_launch(void* const* d_in, const int* in_sizes, int n_in,
                              void* d_out, int out_size) {
    const float* s_emb = (const float*)d_in[0];
    const int*   s_tag = (const int*)d_in[1];
    const int*   s_msk = (const int*)d_in[2];
    const float* q_emb = (const float*)d_in[3];
    const int*   q_msk = (const int*)d_in[4];
    float* out = (float*)d_out;

    k_zero<<<1, 64>>>();
    k_cnt<<<64, 256>>>(s_tag, s_msk);
    dim3 ga(NBLK, KSLABS);
    k_acc2<<<ga, 256>>>(s_emb, s_tag, s_msk);
    dim3 gf(NL, NBLK);
    k_fin2<<<gf, 128>>>();
    k_main<<<512, 128>>>(q_emb, q_msk, out);
}

// round 8
// speedup vs baseline: 1.1971x; 1.1971x over previous
#include <cuda_runtime.h>
#include <cuda_bf16.h>
#include <cstdint>

#define QT 16384
#define ST 16384
#define DD 1024
#define NL 64
#define KSLABS 32          // token slabs (512 tokens each)
#define NBLK   8           // dim blocks (128 dims each)

// ---- scratch (device globals; no allocation allowed) ----
__device__ float          g_part[KSLABS * NL * DD];   // 8 MB partial sums
__device__ float          g_counts[NL];
__device__ __nv_bfloat16  g_protobf[NL * DD];
__device__ float          g_p2[NL];

// ============================================================
// k_zero: zero counts + p2
// ============================================================
__global__ void k_zero() {
    int i = threadIdx.x;
    if (i < NL) { g_counts[i] = 0.f; g_p2[i] = 0.f; }
}

// ============================================================
// k_cnt: masked label histogram. grid 64 x 256 thr.
// ============================================================
__global__ void k_cnt(const int* __restrict__ tag, const int* __restrict__ msk) {
    __shared__ int cnt[NL];
    int t = threadIdx.x;
    if (t < NL) cnt[t] = 0;
    __syncthreads();
    int tk = blockIdx.x * 256 + t;
    if (msk[tk]) atomicAdd(&cnt[tag[tk]], 1);
    __syncthreads();
    if (t < NL && cnt[t]) atomicAdd(&g_counts[t], (float)cnt[t]);
}

// ============================================================
// k_acc2: proto partial sums as a tf32 GEMM (R5 proven form).
// grid (NBLK=8, KSLABS=32) = 256 CTAs, 256 threads (8 warps).
// CTA tile: M=64 labels x N=128 dims, K=512 tokens, chunks of 32.
// Register double-buffered staging, 136-float row pitch.
// ============================================================
__global__ void __launch_bounds__(256, 2) k_acc2(const float* __restrict__ emb,
                                                 const int* __restrict__ tag,
                                                 const int* __restrict__ msk) {
    __shared__ float emb_s[2][32][136];  // 34.8 KB
    __shared__ int   tag_s[2][32];       // tagm = mask? tag : -1

    int t = threadIdx.x;
    int nb = blockIdx.x;                 // dim block 0..7
    int sl = blockIdx.y;                 // token slab 0..31
    int w = t >> 5, l = t & 31;
    int g = l >> 2, tq = l & 3;
    int srow = t >> 3, sseg = t & 7;     // stager: 8 thr per token row
    int nc0 = w * 16;                    // warp dim offset within 128

    const float* ebase = emb + (size_t)(sl * 512) * DD + nb * 128;

    float acc[4][2][4];
    #pragma unroll
    for (int a = 0; a < 4; a++)
        #pragma unroll
        for (int b = 0; b < 2; b++)
            #pragma unroll
            for (int c = 0; c < 4; c++) acc[a][b][c] = 0.f;

    float4 rv[4];
    int rtag, rmsk;

    auto load_chunk = [&](int c) {
        const float* rp = ebase + (size_t)(c * 32 + srow) * DD;
        #pragma unroll
        for (int p = 0; p < 4; p++)
            rv[p] = *reinterpret_cast<const float4*>(rp + (sseg + p * 8) * 4);
        if (t < 32) {
            int tk = sl * 512 + c * 32 + t;
            rtag = __ldg(tag + tk);
            rmsk = __ldg(msk + tk);
        }
    };
    auto store_chunk = [&](int buf) {
        #pragma unroll
        for (int p = 0; p < 4; p++)
            *reinterpret_cast<float4*>(&emb_s[buf][srow][(sseg + p * 8) * 4]) = rv[p];
        if (t < 32) tag_s[buf][t] = rmsk ? rtag : -1;
    };

    load_chunk(0);
    store_chunk(0);

    for (int c = 0; c < 16; c++) {
        __syncthreads();
        if (c < 15) load_chunk(c + 1);
        int cb = c & 1;
        #pragma unroll
        for (int ks = 0; ks < 4; ks++) {
            int k0 = ks * 8;
            int t0 = tag_s[cb][k0 + tq];
            int t1 = tag_s[cb][k0 + tq + 4];
            unsigned b[2][2];
            #pragma unroll
            for (int nt = 0; nt < 2; nt++) {
                b[nt][0] = __float_as_uint(emb_s[cb][k0 + tq][nc0 + nt * 8 + g]);
                b[nt][1] = __float_as_uint(emb_s[cb][k0 + tq + 4][nc0 + nt * 8 + g]);
            }
            #pragma unroll
            for (int mt = 0; mt < 4; mt++) {
                int mlo = mt * 16 + g, mhi = mlo + 8;
                unsigned a0 = (t0 == mlo) ? 0x3F800000u : 0u;
                unsigned a1 = (t0 == mhi) ? 0x3F800000u : 0u;
                unsigned a2 = (t1 == mlo) ? 0x3F800000u : 0u;
                unsigned a3 = (t1 == mhi) ? 0x3F800000u : 0u;
                #pragma unroll
                for (int nt = 0; nt < 2; nt++)
                    asm volatile(
                        "mma.sync.aligned.m16n8k8.row.col.f32.tf32.tf32.f32 "
                        "{%0,%1,%2,%3}, {%4,%5,%6,%7}, {%8,%9}, {%0,%1,%2,%3};\n"
                        : "+f"(acc[mt][nt][0]), "+f"(acc[mt][nt][1]),
                          "+f"(acc[mt][nt][2]), "+f"(acc[mt][nt][3])
                        : "r"(a0), "r"(a1), "r"(a2), "r"(a3),
                          "r"(b[nt][0]), "r"(b[nt][1]));
            }
        }
        if (c < 15) store_chunk((c + 1) & 1);
    }

    // ---- write partial tile: g_part[sl][m][nb*128 + n] ----
    float* pb = g_part + (size_t)sl * NL * DD + nb * 128;
    #pragma unroll
    for (int mt = 0; mt < 4; mt++) {
        int mlo = mt * 16 + g, mhi = mlo + 8;
        #pragma unroll
        for (int nt = 0; nt < 2; nt++) {
            int col = nc0 + nt * 8 + 2 * tq;
            float2 lo = make_float2(acc[mt][nt][0], acc[mt][nt][1]);
            float2 hi = make_float2(acc[mt][nt][2], acc[mt][nt][3]);
            *reinterpret_cast<float2*>(pb + (size_t)mlo * DD + col) = lo;
            *reinterpret_cast<float2*>(pb + (size_t)mhi * DD + col) = hi;
        }
    }
}

// ============================================================
// k_fin2: reduce slabs, divide by counts, emit bf16 proto + p2.
// grid (64 labels, 8 dim-chunks) = 512 CTAs, 128 threads.
// ============================================================
__global__ void __launch_bounds__(128) k_fin2() {
    int n = blockIdx.x, ch = blockIdx.y, t = threadIdx.x;
    int d = ch * 128 + t;
    float s = 0.f;
    const float* pp = g_part + (size_t)n * DD + d;
    #pragma unroll
    for (int sl = 0; sl < KSLABS; sl++)
        s += pp[(size_t)sl * NL * DD];
    float v = s / fmaxf(g_counts[n], 1.f);
    g_protobf[n * DD + d] = __float2bfloat16_rn(v);
    float ps = v * v;
    #pragma unroll
    for (int o = 16; o; o >>= 1) ps += __shfl_xor_sync(0xffffffffu, ps, o);
    if ((t & 31) == 0) atomicAdd(&g_p2[n], ps);
}

// ============================================================
// k_main: 32 tokens x 64 protos per block, 128 threads (4 warps).
// K-chunk = 128 cols (two 64-col halves, R5-proven lane maps),
// register double-buffered. 8 chunks, 8 syncs. grid = 512.
// ============================================================
__global__ void __launch_bounds__(128, 3) k_main(const float* __restrict__ q,
                                                 const int* __restrict__ qmsk,
                                                 float* __restrict__ out) {
    __shared__ __nv_bfloat16 q_sh[2][32][136];   // 17.4 KB
    __shared__ __nv_bfloat16 p_sh[2][64][136];   // 34.8 KB
    __shared__ float q2_sh[32], p2_sh[64];
    __shared__ int   msk_sh[32];

    int t = threadIdx.x;
    int tok0 = blockIdx.x * 32;
    if (t < 64) p2_sh[t] = g_p2[t];
    if (t >= 64 && t < 96) msk_sh[t - 64] = qmsk[tok0 + t - 64];

    int warp = t >> 5, l = t & 31;
    int wm = warp >> 1, wn = warp & 1;
    int g = l >> 2, kb = (l & 3) * 2;
    int lt = t >> 4, kv = t & 15;       // q loader: 16 thr per token row
    int prow = t >> 3, pcol = t & 7;    // proto loader

    const float* qbase = q + (size_t)tok0 * DD;

    float acc[4][4];
    #pragma unroll
    for (int b = 0; b < 4; b++)
        #pragma unroll
        for (int cc = 0; cc < 4; cc++) acc[b][cc] = 0.f;
    float q2p[4] = {0.f, 0.f, 0.f, 0.f};

    float4 vq[2][4];                    // two 64-col halves of the 128-chunk
    uint4  vp[2][4];

    auto load_chunk = [&](int c) {      // c in 0..7 (128 cols each)
        #pragma unroll
        for (int h = 0; h < 2; h++)
            #pragma unroll
            for (int p = 0; p < 4; p++)
                vq[h][p] = *reinterpret_cast<const float4*>(
                    qbase + (size_t)(p * 8 + lt) * DD + c * 128 + h * 64 + kv * 4);
        #pragma unroll
        for (int h = 0; h < 2; h++)
            #pragma unroll
            for (int p = 0; p < 4; p++)
                vp[h][p] = *reinterpret_cast<const uint4*>(
                    &g_protobf[(p * 16 + prow) * DD + c * 128 + h * 64 + pcol * 8]);
    };
    auto store_chunk = [&](int buf) {
        #pragma unroll
        for (int h = 0; h < 2; h++)
            #pragma unroll
            for (int p = 0; p < 4; p++) {
                float4 v = vq[h][p];
                q2p[p] += v.x * v.x + v.y * v.y + v.z * v.z + v.w * v.w;
                __nv_bfloat162 h0 = __floats2bfloat162_rn(v.x, v.y);
                __nv_bfloat162 h1 = __floats2bfloat162_rn(v.z, v.w);
                uint2 u;
                u.x = reinterpret_cast<unsigned&>(h0);
                u.y = reinterpret_cast<unsigned&>(h1);
                *reinterpret_cast<uint2*>(&q_sh[buf][p * 8 + lt][h * 64 + kv * 4]) = u;
            }
        #pragma unroll
        for (int h = 0; h < 2; h++)
            #pragma unroll
            for (int p = 0; p < 4; p++)
                *reinterpret_cast<uint4*>(
                    &p_sh[buf][p * 16 + prow][h * 64 + pcol * 8]) = vp[h][p];
    };

    load_chunk(0);
    store_chunk(0);

    for (int c = 0; c < 8; c++) {
        __syncthreads();
        if (c < 7) load_chunk(c + 1);   // 16 LDGs in flight over 8 MMA subiters
        int cb = c & 1;
        #pragma unroll
        for (int s = 0; s < 8; s++) {
            int k0 = s * 16 + kb;
            unsigned a[4], b[4][2];
            {
                int r = wm * 16 + g;
                a[0] = *reinterpret_cast<const unsigned*>(&q_sh[cb][r][k0]);
                a[1] = *reinterpret_cast<const unsigned*>(&q_sh[cb][r + 8][k0]);
                a[2] = *reinterpret_cast<const unsigned*>(&q_sh[cb][r][k0 + 8]);
                a[3] = *reinterpret_cast<const unsigned*>(&q_sh[cb][r + 8][k0 + 8]);
            }
            #pragma unroll
            for (int nt = 0; nt < 4; nt++) {
                int n0 = wn * 32 + nt * 8 + g;
                b[nt][0] = *reinterpret_cast<const unsigned*>(&p_sh[cb][n0][k0]);
                b[nt][1] = *reinterpret_cast<const unsigned*>(&p_sh[cb][n0][k0 + 8]);
            }
            #pragma unroll
            for (int nt = 0; nt < 4; nt++)
                asm volatile(
                    "mma.sync.aligned.m16n8k16.row.col.f32.bf16.bf16.f32 "
                    "{%0,%1,%2,%3}, {%4,%5,%6,%7}, {%8,%9}, {%0,%1,%2,%3};\n"
                    : "+f"(acc[nt][0]), "+f"(acc[nt][1]),
                      "+f"(acc[nt][2]), "+f"(acc[nt][3])
                    : "r"(a[0]), "r"(a[1]), "r"(a[2]), "r"(a[3]),
                      "r"(b[nt][0]), "r"(b[nt][1]));
        }
        if (c < 7) store_chunk((c + 1) & 1);
    }

    // ---- fold per-thread q2 partials (16 lanes per token row) ----
    #pragma unroll
    for (int p = 0; p < 4; p++) {
        float vv = q2p[p];
        vv += __shfl_xor_sync(0xffffffffu, vv, 8);
        vv += __shfl_xor_sync(0xffffffffu, vv, 4);
        vv += __shfl_xor_sync(0xffffffffu, vv, 2);
        vv += __shfl_xor_sync(0xffffffffu, vv, 1);
        if (kv == 0) q2_sh[p * 8 + lt] = vv;
    }
    __syncthreads();

    // ---- epilogue ----
    {
        int r0 = wm * 16 + g;
        int r1 = r0 + 8;
        float m0 = (float)msk_sh[r0], m1 = (float)msk_sh[r1];
        float q20 = q2_sh[r0], q21 = q2_sh[r1];
        #pragma unroll
        for (int nt = 0; nt < 4; nt++) {
            int cc = wn * 32 + nt * 8 + kb;
            float p20 = p2_sh[cc], p21 = p2_sh[cc + 1];
            float2 o0, o1;
            o0.x = -(q20 + p20 - 2.f * acc[nt][0]) * m0;
            o0.y = -(q20 + p21 - 2.f * acc[nt][1]) * m0;
            o1.x = -(q21 + p20 - 2.f * acc[nt][2]) * m1;
            o1.y = -(q21 + p21 - 2.f * acc[nt][3]) * m1;
            *reinterpret_cast<float2*>(out + (size_t)(tok0 + r0) * NL + cc) = o0;
            *reinterpret_cast<float2*>(out + (size_t)(tok0 + r1) * NL + cc) = o1;
        }
    }
}

// ============================================================
extern "C" void kernel_launch(void* const* d_in, const int* in_sizes, int n_in,
                              void* d_out, int out_size) {
    const float* s_emb = (const float*)d_in[0];
    const int*   s_tag = (const int*)d_in[1];
    const int*   s_msk = (const int*)d_in[2];
    const float* q_emb = (const float*)d_in[3];
    const int*   q_msk = (const int*)d_in[4];
    float* out = (float*)d_out;

    k_zero<<<1, 64>>>();
    k_cnt<<<64, 256>>>(s_tag, s_msk);
    dim3 ga(NBLK, KSLABS);
    k_acc2<<<ga, 256>>>(s_emb, s_tag, s_msk);
    dim3 gf(NL, NBLK);
    k_fin2<<<gf, 128>>>();
    k_main<<<512, 128>>>(q_emb, q_msk, out);
}